// round 4
// baseline (speedup 1.0000x reference)
#include <cuda_runtime.h>
#include <cuda_bf16.h>
#include <cstddef>

// Shapes: user [B=32, U=128, D=256] fp32, image [B=32, I=256, D=256] fp32
// out = concat(user * img_sum[b,1,:], image * user_sum[b,1,:])
//
// Flavor-split design: out_user depends only on img_sum, out_img only on
// user_sum -> two independent CTA flavors, 1024 tiny CTAs total, one wave.

#define BB 32
#define UU 128
#define II 256
#define DD 256

#define DCH 16               // floats per CTA chunk
#define NCH (DD / DCH)       // 16
#define NT 256               // threads per CTA
#define NWARPS (NT / 32)     // 8
#define HALF_GRID (BB * NCH) // 512
#define GRID (2 * HALF_GRID) // 1024

__device__ __forceinline__ float4 f4add(float4 a, float4 b) {
    return make_float4(a.x + b.x, a.y + b.y, a.z + b.z, a.w + b.w);
}
__device__ __forceinline__ float4 f4mul(float4 a, float4 b) {
    return make_float4(a.x * b.x, a.y * b.y, a.z * b.z, a.w * b.w);
}

__global__ __launch_bounds__(NT)
void ExternalInteraction_65609920413984_kernel(
    const float* __restrict__ user,
    const float* __restrict__ img,
    float* __restrict__ out_user,
    float* __restrict__ out_img)
{
    __shared__ float4 ws[NWARPS][4];

    const int bid   = blockIdx.x;
    const bool flavU = bid < HALF_GRID;          // true: produce out_user
    const int id    = flavU ? bid : bid - HALF_GRID;
    const int b     = id >> 4;                   // / NCH
    const int d0    = (id & (NCH - 1)) * DCH;

    const int tx   = threadIdx.x & 3;            // float4 lane (16 floats wide)
    const int ty   = threadIdx.x >> 2;           // 0..63 row group
    const int warp = threadIdx.x >> 5;
    const int lane = threadIdx.x & 31;
    const int d    = d0 + tx * 4;
    const int rs   = DD / 4;                     // row stride in float4

    const float4* up = reinterpret_cast<const float4*>(user + (size_t)b * UU * DD + d);
    const float4* ip = reinterpret_cast<const float4*>(img  + (size_t)b * II * DD + d);
    float4* ou = reinterpret_cast<float4*>(out_user + (size_t)b * UU * DD + d);
    float4* oi = reinterpret_cast<float4*>(out_img  + (size_t)b * II * DD + d);

    // ---- Phase 1: partial column sums (4 or 2 independent loads/thread) ----
    float4 a = make_float4(0.f, 0.f, 0.f, 0.f);
    if (flavU) {
        #pragma unroll
        for (int k = 0; k < II / 64; k++)        // 4 loads over image rows
            a = f4add(a, ip[(size_t)(ty + 64 * k) * rs]);
    } else {
        #pragma unroll
        for (int k = 0; k < UU / 64; k++)        // 2 loads over user rows
            a = f4add(a, up[(size_t)(ty + 64 * k) * rs]);
    }

    // Intra-warp reduction over the 8 ty-subrows (tx invariant under xor 4/8/16)
    #pragma unroll
    for (int m = 4; m < 32; m <<= 1) {
        a.x += __shfl_xor_sync(0xffffffffu, a.x, m);
        a.y += __shfl_xor_sync(0xffffffffu, a.y, m);
        a.z += __shfl_xor_sync(0xffffffffu, a.z, m);
        a.w += __shfl_xor_sync(0xffffffffu, a.w, m);
    }
    if (lane < 4) ws[warp][tx] = a;
    __syncthreads();

    // Every thread sums the 8 warp partials (broadcast LDS, no 2nd barrier)
    float4 s = ws[0][tx];
    #pragma unroll
    for (int w = 1; w < NWARPS; w++) s = f4add(s, ws[w][tx]);

    // ---- Phase 2: scale + store the other tensor ----
    if (flavU) {
        float4 v0 = up[(size_t)(ty +  0) * rs];
        float4 v1 = up[(size_t)(ty + 64) * rs];
        ou[(size_t)(ty +  0) * rs] = f4mul(v0, s);
        ou[(size_t)(ty + 64) * rs] = f4mul(v1, s);
    } else {
        float4 v0 = ip[(size_t)(ty +   0) * rs];
        float4 v1 = ip[(size_t)(ty +  64) * rs];
        float4 v2 = ip[(size_t)(ty + 128) * rs];
        float4 v3 = ip[(size_t)(ty + 192) * rs];
        oi[(size_t)(ty +   0) * rs] = f4mul(v0, s);
        oi[(size_t)(ty +  64) * rs] = f4mul(v1, s);
        oi[(size_t)(ty + 128) * rs] = f4mul(v2, s);
        oi[(size_t)(ty + 192) * rs] = f4mul(v3, s);
    }
}

extern "C" void kernel_launch(void* const* d_in, const int* in_sizes, int n_in,
                              void* d_out, int out_size)
{
    (void)in_sizes; (void)n_in; (void)out_size;
    const float* user = (const float*)d_in[0];
    const float* img  = (const float*)d_in[1];
    float* out_user = (float*)d_out;
    float* out_img  = (float*)d_out + (size_t)BB * UU * DD;

    ExternalInteraction_65609920413984_kernel
        <<<GRID, NT>>>(user, img, out_user, out_img);
}

// round 5
// speedup vs baseline: 1.2259x; 1.2259x over previous
#include <cuda_runtime.h>
#include <cuda_bf16.h>
#include <cstddef>

// Shapes: user [B=32, U=128, D=256] fp32, image [B=32, I=256, D=256] fp32
// out = concat(user * img_sum[b,1,:], image * user_sum[b,1,:])
//
// Read-once fused kernel, single load-wait + single barrier on the critical
// path. All 12 input rows per thread loaded up front into registers (MLP=12),
// both column sums reduced together, all stores fired from registers.

#define BB 32
#define UU 128
#define II 256
#define DD 256

#define TX 8                 // float4 lanes: 32 floats = 128B rows per warp
#define TY 32                // row groups
#define NT (TX * TY)         // 256 threads
#define DCH 32               // d-chunk per CTA
#define NCH (DD / DCH)       // 8
#define GRID (BB * NCH)      // 256
#define NWARPS (NT / 32)     // 8

__device__ __forceinline__ float4 f4add(float4 a, float4 b) {
    return make_float4(a.x + b.x, a.y + b.y, a.z + b.z, a.w + b.w);
}
__device__ __forceinline__ float4 f4mul(float4 a, float4 b) {
    return make_float4(a.x * b.x, a.y * b.y, a.z * b.z, a.w * b.w);
}
__device__ __forceinline__ void f4shfl_acc(float4& a, int m) {
    a.x += __shfl_xor_sync(0xffffffffu, a.x, m);
    a.y += __shfl_xor_sync(0xffffffffu, a.y, m);
    a.z += __shfl_xor_sync(0xffffffffu, a.z, m);
    a.w += __shfl_xor_sync(0xffffffffu, a.w, m);
}

__global__ __launch_bounds__(NT)
void ExternalInteraction_65609920413984_kernel(
    const float* __restrict__ user,
    const float* __restrict__ img,
    float* __restrict__ out_user,
    float* __restrict__ out_img)
{
    __shared__ float4 wsI[NWARPS][TX];   // per-warp image partials
    __shared__ float4 wsU[NWARPS][TX];   // per-warp user  partials

    const int b  = blockIdx.x >> 3;               // / NCH
    const int d0 = (blockIdx.x & (NCH - 1)) * DCH;
    const int tx = threadIdx.x & (TX - 1);
    const int ty = threadIdx.x >> 3;
    const int warp = threadIdx.x >> 5;
    const int lane = threadIdx.x & 31;
    const int d  = d0 + tx * 4;
    const int rs = DD / 4;                        // row stride in float4

    const float4* up = reinterpret_cast<const float4*>(user + (size_t)b * UU * DD + d);
    const float4* ip = reinterpret_cast<const float4*>(img  + (size_t)b * II * DD + d);
    float4* ou = reinterpret_cast<float4*>(out_user + (size_t)b * UU * DD + d);
    float4* oi = reinterpret_cast<float4*>(out_img  + (size_t)b * II * DD + d);

    // ---- Phase A: issue ALL loads up front (12 independent float4 / thread)
    float4 iv[II / TY];   // 8
    float4 uv[UU / TY];   // 4
    #pragma unroll
    for (int k = 0; k < II / TY; k++)
        iv[k] = ip[(size_t)(ty + k * TY) * rs];
    #pragma unroll
    for (int k = 0; k < UU / TY; k++)
        uv[k] = up[(size_t)(ty + k * TY) * rs];

    // ---- Phase B: both partial sums from registers
    float4 ai = iv[0];
    #pragma unroll
    for (int k = 1; k < II / TY; k++) ai = f4add(ai, iv[k]);
    float4 au = uv[0];
    #pragma unroll
    for (int k = 1; k < UU / TY; k++) au = f4add(au, uv[k]);

    // Intra-warp: reduce over the 4 ty-subrows sharing each tx (xor 8, 16)
    f4shfl_acc(ai, 8);  f4shfl_acc(ai, 16);
    f4shfl_acc(au, 8);  f4shfl_acc(au, 16);

    if (lane < TX) { wsI[warp][tx] = ai; wsU[warp][tx] = au; }
    __syncthreads();                       // the ONLY barrier

    // Cross-warp: every thread sums the 8 warp partials (broadcast LDS)
    float4 is = wsI[0][tx];
    float4 us = wsU[0][tx];
    #pragma unroll
    for (int w = 1; w < NWARPS; w++) {
        is = f4add(is, wsI[w][tx]);
        us = f4add(us, wsU[w][tx]);
    }

    // ---- Phase C: all stores straight from registers
    #pragma unroll
    for (int k = 0; k < UU / TY; k++)
        ou[(size_t)(ty + k * TY) * rs] = f4mul(uv[k], is);
    #pragma unroll
    for (int k = 0; k < II / TY; k++)
        oi[(size_t)(ty + k * TY) * rs] = f4mul(iv[k], us);
}

extern "C" void kernel_launch(void* const* d_in, const int* in_sizes, int n_in,
                              void* d_out, int out_size)
{
    (void)in_sizes; (void)n_in; (void)out_size;
    const float* user = (const float*)d_in[0];
    const float* img  = (const float*)d_in[1];
    float* out_user = (float*)d_out;
    float* out_img  = (float*)d_out + (size_t)BB * UU * DD;

    ExternalInteraction_65609920413984_kernel
        <<<GRID, NT>>>(user, img, out_user, out_img);
}